// round 1
// baseline (speedup 1.0000x reference)
#include <cuda_runtime.h>
#include <cuda_bf16.h>

// AffineAugment: per-batch rigid affine warp of [B,H,W,D,1] fp32 volume,
// trilinear interpolation, zero fill outside [0, dim-1] on any axis.
// Shapes fixed by the problem: B=4, H=W=D=192, C=1.
//
// loc = mats[b][:, :3] @ [i,j,k] + mats[b][:, 3]   (voxel coords)
// valid iff all axes in [0, dim-1] (inclusive, float compare, matches ref)

#define BB  4
#define HH  192
#define WW  192
#define DD  192
#define ZPT 4            // outputs per thread along D (float4 store)

__global__ void __launch_bounds__(256)
affine_warp_kernel(const float* __restrict__ x,
                   const float* __restrict__ mats,
                   float* __restrict__ out)
{
    const int groups_per_row = DD / ZPT;                       // 48
    const int total_groups   = BB * HH * WW * groups_per_row;  // 7,077,888

    int gid = blockIdx.x * blockDim.x + threadIdx.x;
    if (gid >= total_groups) return;

    int g  = gid % groups_per_row;
    int t  = gid / groups_per_row;
    int j  = t % WW;  t /= WW;
    int i  = t % HH;
    int b  = t / HH;
    int k0 = g * ZPT;

    // mats[b] is row-major [3][4]
    const float* __restrict__ M = mats + b * 12;
    const float m00 = __ldg(M + 0), m01 = __ldg(M + 1), m02 = __ldg(M + 2), m03 = __ldg(M + 3);
    const float m10 = __ldg(M + 4), m11 = __ldg(M + 5), m12 = __ldg(M + 6), m13 = __ldg(M + 7);
    const float m20 = __ldg(M + 8), m21 = __ldg(M + 9), m22 = __ldg(M +10), m23 = __ldg(M +11);

    const float fi = (float)i, fj = (float)j;
    // base location at k=0 (i,j fixed for this thread)
    const float b0 = fmaf(m00, fi, fmaf(m01, fj, m03));
    const float b1 = fmaf(m10, fi, fmaf(m11, fj, m13));
    const float b2 = fmaf(m20, fi, fmaf(m21, fj, m23));

    const float* __restrict__ vb = x + (size_t)b * (HH * WW * DD);

    float res[ZPT];

#pragma unroll
    for (int z = 0; z < ZPT; z++) {
        const float fk = (float)(k0 + z);
        const float lx = fmaf(m02, fk, b0);
        const float ly = fmaf(m12, fk, b1);
        const float lz = fmaf(m22, fk, b2);

        float v = 0.0f;
        const bool valid =
            (lx >= 0.0f) & (lx <= (float)(HH - 1)) &
            (ly >= 0.0f) & (ly <= (float)(WW - 1)) &
            (lz >= 0.0f) & (lz <= (float)(DD - 1));

        if (valid) {
            const float fx = floorf(lx), fy = floorf(ly), fz = floorf(lz);
            const float tx = lx - fx, ty = ly - fy, tz = lz - fz;

            int ix0 = (int)fx, iy0 = (int)fy, iz0 = (int)fz;
            int ix1 = min(ix0 + 1, HH - 1);
            int iy1 = min(iy0 + 1, WW - 1);
            int iz1 = min(iz0 + 1, DD - 1);

            const int r00 = (ix0 * WW + iy0) * DD;
            const int r01 = (ix0 * WW + iy1) * DD;
            const int r10 = (ix1 * WW + iy0) * DD;
            const int r11 = (ix1 * WW + iy1) * DD;

            const float c000 = __ldg(vb + r00 + iz0);
            const float c001 = __ldg(vb + r00 + iz1);
            const float c010 = __ldg(vb + r01 + iz0);
            const float c011 = __ldg(vb + r01 + iz1);
            const float c100 = __ldg(vb + r10 + iz0);
            const float c101 = __ldg(vb + r10 + iz1);
            const float c110 = __ldg(vb + r11 + iz0);
            const float c111 = __ldg(vb + r11 + iz1);

            // lerp z, then y, then x
            const float c00 = fmaf(tz, c001 - c000, c000);
            const float c01 = fmaf(tz, c011 - c010, c010);
            const float c10 = fmaf(tz, c101 - c100, c100);
            const float c11 = fmaf(tz, c111 - c110, c110);
            const float c0  = fmaf(ty, c01 - c00, c00);
            const float c1  = fmaf(ty, c11 - c10, c10);
            v = fmaf(tx, c1 - c0, c0);
        }
        res[z] = v;
    }

    // coalesced vector store: k0 % 4 == 0, DD % 4 == 0 → 16B aligned
    float4* o4 = (float4*)(out + ((size_t)((b * HH + i) * WW + j) * DD + k0));
    *o4 = make_float4(res[0], res[1], res[2], res[3]);
}

extern "C" void kernel_launch(void* const* d_in, const int* in_sizes, int n_in,
                              void* d_out, int out_size)
{
    const float* x    = (const float*)d_in[0];
    const float* mats = (const float*)d_in[1];
    float* out        = (float*)d_out;

    const int total_groups = BB * HH * WW * (DD / ZPT);
    const int threads = 256;
    const int blocks  = (total_groups + threads - 1) / threads;
    affine_warp_kernel<<<blocks, threads>>>(x, mats, out);
}